// round 7
// baseline (speedup 1.0000x reference)
#include <cuda_runtime.h>
#include <cstdint>

#define B 64
#define K 8
#define V 128000
#define NV4    32000                 // float4 per row
#define SPLIT  5                     // CTAs per row in k2a
#define NWARP  8                     // warps per CTA in k2a
#define NCHUNK (SPLIT * NWARP)       // 40 warp-chunks per row
#define CHUNK4 (NV4 / NCHUNK)        // 800 float4 per chunk (3200 elems)
#define LANE4  (CHUNK4 / 32)         // 25 float4 per lane in k2b refinement

// cross-kernel scratch (no allocations allowed)
__device__ int    g_j[B];
__device__ float  g_u[B];
__device__ int    g_num[B];
__device__ int    g_all[B];
__device__ double g_csum[B * NCHUNK];
__device__ float  g_amv[B * SPLIT];
__device__ int    g_ami[B * SPLIT];

// ---------------------------------------------------------------------------
// Kernel 1: accept chain + bookkeeping outputs (float32 output buffer!).
// ---------------------------------------------------------------------------
__global__ void k1_accept(const int* __restrict__ draft_ids,
                          const float* __restrict__ draft_probs,
                          const float* __restrict__ target_probs,
                          const int* __restrict__ bonus,
                          const float* __restrict__ uniforms,
                          float* __restrict__ out, int out_size) {
    int b = threadIdx.x;
    if (b >= B) return;

    int ids[K];
    int num = 0;
    bool chain = true;
#pragma unroll
    for (int k = 0; k < K; k++) {
        int id = draft_ids[b * K + k];
        ids[k] = id;
        size_t base = (size_t)(b * K + k) * (size_t)V + (size_t)id;
        float p = target_probs[base];
        float q = draft_probs[base];
        float ap = fminf(1.0f, __fdiv_rn(p, fmaxf(q, 1e-10f)));  // bit-exact vs ref
        bool a = uniforms[b * K + k] < ap;
        chain = chain && a;
        num += chain ? 1 : 0;
    }
    int j   = (num < K - 1) ? num : (K - 1);
    int all = (num == K) ? 1 : 0;

    g_j[b]   = j;
    g_u[b]   = uniforms[b * K + j];
    g_num[b] = num;
    g_all[b] = all;

    float* row = out + b * (K + 1);
#pragma unroll
    for (int pos = 0; pos <= K; pos++) {
        float v;
        if (pos < num)       v = (float)ids[pos];
        else if (pos == num) v = all ? (float)bonus[b] : -1.0f;  // k2b fills recovered
        else                 v = -1.0f;
        row[pos] = v;
    }
    if (out_size >= B * (K + 1) + 4 * B) {
        out[B * (K + 1) + 0 * B + b] = (float)num;
        out[B * (K + 1) + 1 * B + b] = (float)num;
        out[B * (K + 1) + 2 * B + b] = (float)(1 - all);
        out[B * (K + 1) + 3 * B + b] = (float)all;
    }
}

// ---------------------------------------------------------------------------
// Kernel 2a: DRAM pass. SPLIT CTAs per row; each warp sums one 800-float4
// chunk of residuals (fp64) and contributes to a per-CTA argmax fallback.
// ---------------------------------------------------------------------------
__global__ void __launch_bounds__(NWARP * 32)
k2a_sums(const float* __restrict__ draft_probs,
         const float* __restrict__ target_probs) {
    int bb = blockIdx.x;
    int b = bb / SPLIT, s = bb % SPLIT;
    if (g_all[b]) return;

    int j = g_j[b];
    const float4* tg = reinterpret_cast<const float4*>(
        target_probs + ((size_t)b * K + (size_t)j) * (size_t)V);
    const float4* dr = reinterpret_cast<const float4*>(
        draft_probs + ((size_t)b * K + (size_t)j) * (size_t)V);

    int tid = threadIdx.x, w = tid >> 5, lane = tid & 31;
    int cb = (s * NWARP + w) * CHUNK4;

    double part = 0.0;
    float  mv = -1.0f;
    int    mi = 0;
#pragma unroll 5
    for (int i = lane; i < CHUNK4; i += 32) {
        float4 t4 = tg[cb + i];
        float4 d4 = dr[cb + i];
        part += (double)fmaxf(t4.x - d4.x, 0.0f);
        part += (double)fmaxf(t4.y - d4.y, 0.0f);
        part += (double)fmaxf(t4.z - d4.z, 0.0f);
        part += (double)fmaxf(t4.w - d4.w, 0.0f);
        int e = (cb + i) * 4;
        if (t4.x > mv) { mv = t4.x; mi = e; }     else if (t4.x == mv && e     < mi) mi = e;
        if (t4.y > mv) { mv = t4.y; mi = e + 1; } else if (t4.y == mv && e + 1 < mi) mi = e + 1;
        if (t4.z > mv) { mv = t4.z; mi = e + 2; } else if (t4.z == mv && e + 2 < mi) mi = e + 2;
        if (t4.w > mv) { mv = t4.w; mi = e + 3; } else if (t4.w == mv && e + 3 < mi) mi = e + 3;
    }
#pragma unroll
    for (int off = 16; off; off >>= 1) {
        part += __shfl_down_sync(0xffffffffu, part, off);
        float ov = __shfl_down_sync(0xffffffffu, mv, off);
        int   oi = __shfl_down_sync(0xffffffffu, mi, off);
        if (ov > mv || (ov == mv && oi < mi)) { mv = ov; mi = oi; }
    }

    __shared__ float s_mv[NWARP];
    __shared__ int   s_mi[NWARP];
    if (lane == 0) {
        g_csum[b * NCHUNK + s * NWARP + w] = part;
        s_mv[w] = mv;
        s_mi[w] = mi;
    }
    __syncthreads();
    if (tid == 0) {
        float bm = s_mv[0]; int bi = s_mi[0];
        for (int c = 1; c < NWARP; c++)
            if (s_mv[c] > bm || (s_mv[c] == bm && s_mi[c] < bi)) { bm = s_mv[c]; bi = s_mi[c]; }
        g_amv[bb] = bm;
        g_ami[bb] = bi;
    }
}

// ---------------------------------------------------------------------------
// Kernel 2b: one warp per row. Scan 40 chunk sums -> crossing chunk; refine
// 800 float4 (L2-hot) with per-lane sums + warp scan; crossing lane walks
// its 25 float4 sequentially for the exact element.
// ---------------------------------------------------------------------------
__global__ void __launch_bounds__(32)
k2b_pick(const float* __restrict__ draft_probs,
         const float* __restrict__ target_probs,
         float* __restrict__ out) {
    int b = blockIdx.x;
    if (g_all[b]) return;

    int lane = threadIdx.x;
    int j = g_j[b];
    float u = g_u[b];
    const float4* tg = reinterpret_cast<const float4*>(
        target_probs + ((size_t)b * K + (size_t)j) * (size_t)V);
    const float4* dr = reinterpret_cast<const float4*>(
        draft_probs + ((size_t)b * K + (size_t)j) * (size_t)V);

    int    c = 0, done = 0, res = 0;
    double t = 0.0, base = 0.0;
    if (lane == 0) {
        double total = 0.0;
        for (int cc = 0; cc < NCHUNK; cc++) total += g_csum[b * NCHUNK + cc];
        if (!(total > 0.0)) {
            // fallback: argmax of target row (first max)
            float bm = g_amv[b * SPLIT]; int bi = g_ami[b * SPLIT];
            for (int ss = 1; ss < SPLIT; ss++) {
                float v = g_amv[b * SPLIT + ss]; int i2 = g_ami[b * SPLIT + ss];
                if (v > bm || (v == bm && i2 < bi)) { bm = v; bi = i2; }
            }
            res = bi; done = 1;
        } else {
            t = (double)u * total;
            double run = 0.0;
            c = -1;
            for (int cc = 0; cc < NCHUNK; cc++) {
                double cs = g_csum[b * NCHUNK + cc];
                if (run + cs > t) { c = cc; break; }
                run += cs;
            }
            if (c < 0) {  // fp edge: clamp to last chunk
                c = NCHUNK - 1;
                run = total - g_csum[b * NCHUNK + NCHUNK - 1];
            }
            base = run;
        }
    }
    done = __shfl_sync(0xffffffffu, done, 0);
    if (done) {
        if (lane == 0) out[b * (K + 1) + g_num[b]] = (float)res;
        return;
    }
    c    = __shfl_sync(0xffffffffu, c, 0);
    t    = __shfl_sync(0xffffffffu, t, 0);
    base = __shfl_sync(0xffffffffu, base, 0);

    // per-lane contiguous sub-chunk sums (25 float4 each)
    int lb = c * CHUNK4 + lane * LANE4;
    double lsum = 0.0;
#pragma unroll
    for (int k2 = 0; k2 < LANE4; k2++) {
        float4 t4 = tg[lb + k2];
        float4 d4 = dr[lb + k2];
        lsum += (double)fmaxf(t4.x - d4.x, 0.0f);
        lsum += (double)fmaxf(t4.y - d4.y, 0.0f);
        lsum += (double)fmaxf(t4.z - d4.z, 0.0f);
        lsum += (double)fmaxf(t4.w - d4.w, 0.0f);
    }
    // inclusive warp scan
    double sc = lsum;
#pragma unroll
    for (int off = 1; off < 32; off <<= 1) {
        double o = __shfl_up_sync(0xffffffffu, sc, off);
        if (lane >= off) sc += o;
    }
    unsigned m = __ballot_sync(0xffffffffu, (base + sc) > t);
    int fl = m ? (__ffs(m) - 1) : 31;  // clamp to last lane on fp edge

    if (lane == fl) {
        double run = base + (sc - lsum);   // exclusive prefix for this lane
        int idx = (lb + LANE4 - 1) * 4 + 3;  // clamp default: last element
        for (int k2 = 0; k2 < LANE4; k2++) {
            float4 t4 = tg[lb + k2];
            float4 d4 = dr[lb + k2];
            double r0 = (double)fmaxf(t4.x - d4.x, 0.0f);
            double p1 = r0 + (double)fmaxf(t4.y - d4.y, 0.0f);
            double p2 = p1 + (double)fmaxf(t4.z - d4.z, 0.0f);
            double p3 = p2 + (double)fmaxf(t4.w - d4.w, 0.0f);
            int e = (lb + k2) * 4;
            if      (run + r0 > t) { idx = e;     break; }
            else if (run + p1 > t) { idx = e + 1; break; }
            else if (run + p2 > t) { idx = e + 2; break; }
            else if (run + p3 > t) { idx = e + 3; break; }
            run += p3;
        }
        out[b * (K + 1) + g_num[b]] = (float)idx;
    }
}

// ---------------------------------------------------------------------------
extern "C" void kernel_launch(void* const* d_in, const int* in_sizes, int n_in,
                              void* d_out, int out_size) {
    const int*   draft_ids    = (const int*)d_in[0];
    const float* draft_probs  = (const float*)d_in[1];
    const float* target_probs = (const float*)d_in[2];
    const int*   bonus        = (const int*)d_in[3];
    const float* uniforms     = (const float*)d_in[4];
    float* out = (float*)d_out;

    k1_accept<<<1, B>>>(draft_ids, draft_probs, target_probs, bonus, uniforms,
                        out, out_size);
    k2a_sums<<<B * SPLIT, NWARP * 32>>>(draft_probs, target_probs);
    k2b_pick<<<B, 32>>>(draft_probs, target_probs, out);
}

// round 8
// speedup vs baseline: 2.3829x; 2.3829x over previous
#include <cuda_runtime.h>
#include <cstdint>

#define B 64
#define K 8
#define V 128000
#define NV4    32000                 // float4 per row
#define SPLIT  5                     // CTAs per row in k2a
#define NWARP  8                     // warps per CTA in k2a
#define NCHUNK (SPLIT * NWARP)       // 40 warp-chunks per row
#define CHUNK4 (NV4 / NCHUNK)        // 800 float4 per chunk (3200 elems)
#define LANE4  (CHUNK4 / 32)         // 25 float4 per lane in k2b refinement

// cross-kernel scratch (no allocations allowed)
__device__ int   g_j[B];
__device__ float g_u[B];
__device__ int   g_num[B];
__device__ int   g_all[B];
__device__ float g_csum[B * NCHUNK];

// ---------------------------------------------------------------------------
// Kernel 1: accept chain, parallel over (b,k). 512 threads, 1 CTA.
// Lanes grp..grp+7 of each warp form one row; ballot gives the accept bits.
// Output buffer dtype is float32 — store VALUES as floats.
// ---------------------------------------------------------------------------
__global__ void __launch_bounds__(B * K)
k1_accept(const int* __restrict__ draft_ids,
          const float* __restrict__ draft_probs,
          const float* __restrict__ target_probs,
          const int* __restrict__ bonus,
          const float* __restrict__ uniforms,
          float* __restrict__ out, int out_size) {
    int tid  = threadIdx.x;            // 0..511
    int b    = tid >> 3;
    int k    = tid & 7;
    int lane = tid & 31;
    int grp  = lane & ~7;              // first lane of this row's group

    int   id = draft_ids[tid];
    float u  = uniforms[tid];
    size_t base = (size_t)tid * (size_t)V + (size_t)id;
    float p = target_probs[base];
    float q = draft_probs[base];
    float ap  = fminf(1.0f, __fdiv_rn(p, fmaxf(q, 1e-10f)));  // bit-exact vs ref
    bool  acc = u < ap;

    unsigned m = __ballot_sync(0xffffffffu, acc);
    unsigned rowbits = (m >> grp) & 0xFFu;
    int num = __ffs(~rowbits) - 1;     // leading run of accepts, 0..8
    int j   = (num < K - 1) ? num : (K - 1);
    int all = (num == K) ? 1 : 0;

    float uj = __shfl_sync(0xffffffffu, u, grp + j);

    int bon = (k == 0) ? bonus[b] : 0;
    bon = __shfl_sync(0xffffffffu, bon, grp);
    float lastval = all ? (float)bon : -1.0f;  // !all slot filled later by k2b

    // each lane writes its own position; lane k==0 also writes pos K + scalars
    float v = (k < num) ? (float)id : ((k == num) ? lastval : -1.0f);
    out[b * (K + 1) + k] = v;
    if (k == 0) {
        out[b * (K + 1) + K] = (num == K) ? lastval : -1.0f;
        g_j[b]   = j;
        g_u[b]   = uj;
        g_num[b] = num;
        g_all[b] = all;
        if (out_size >= B * (K + 1) + 4 * B) {
            out[B * (K + 1) + 0 * B + b] = (float)num;
            out[B * (K + 1) + 1 * B + b] = (float)num;
            out[B * (K + 1) + 2 * B + b] = (float)(1 - all);
            out[B * (K + 1) + 3 * B + b] = (float)all;
        }
    }
}

// ---------------------------------------------------------------------------
// Kernel 2a: DRAM pass, fp32 only (fp64 pipe was the R7 bottleneck: ~53us).
// SPLIT CTAs per row; each warp tree-sums one 800-float4 chunk of residuals.
// ---------------------------------------------------------------------------
__global__ void __launch_bounds__(NWARP * 32)
k2a_sums(const float* __restrict__ draft_probs,
         const float* __restrict__ target_probs) {
    int bb = blockIdx.x;
    int b = bb / SPLIT, s = bb % SPLIT;
    if (g_all[b]) return;

    int j = g_j[b];
    const float4* tg = reinterpret_cast<const float4*>(
        target_probs + ((size_t)b * K + (size_t)j) * (size_t)V);
    const float4* dr = reinterpret_cast<const float4*>(
        draft_probs + ((size_t)b * K + (size_t)j) * (size_t)V);

    int tid = threadIdx.x, w = tid >> 5, lane = tid & 31;
    int cb = (s * NWARP + w) * CHUNK4;

    float part = 0.0f;
#pragma unroll 5
    for (int i = lane; i < CHUNK4; i += 32) {
        float4 t4 = tg[cb + i];
        float4 d4 = dr[cb + i];
        part += fmaxf(t4.x - d4.x, 0.0f) + fmaxf(t4.y - d4.y, 0.0f)
              + fmaxf(t4.z - d4.z, 0.0f) + fmaxf(t4.w - d4.w, 0.0f);
    }
#pragma unroll
    for (int off = 16; off; off >>= 1)
        part += __shfl_down_sync(0xffffffffu, part, off);
    if (lane == 0)
        g_csum[b * NCHUNK + s * NWARP + w] = part;
}

// ---------------------------------------------------------------------------
// Kernel 2b: one warp per row. Combine 40 chunk sums (fp64, cheap) -> pick
// crossing chunk; refine with fp32 lane sums + fp64 scan; crossing lane
// walks its 25 float4 for the exact element. Argmax fallback (total<=0,
// never taken on softmax data) scans the full row here.
// ---------------------------------------------------------------------------
__global__ void __launch_bounds__(32)
k2b_pick(const float* __restrict__ draft_probs,
         const float* __restrict__ target_probs,
         float* __restrict__ out) {
    int b = blockIdx.x;
    if (g_all[b]) return;

    int lane = threadIdx.x;
    int j = g_j[b];
    float u = g_u[b];
    const float4* tg = reinterpret_cast<const float4*>(
        target_probs + ((size_t)b * K + (size_t)j) * (size_t)V);
    const float4* dr = reinterpret_cast<const float4*>(
        draft_probs + ((size_t)b * K + (size_t)j) * (size_t)V);

    int    c = 0, done = 0;
    double t = 0.0, base = 0.0;
    if (lane == 0) {
        double total = 0.0;
        for (int cc = 0; cc < NCHUNK; cc++) total += (double)g_csum[b * NCHUNK + cc];
        if (!(total > 0.0)) {
            done = 1;  // fallback handled below by whole warp
        } else {
            t = (double)u * total;
            double run = 0.0;
            c = -1;
            for (int cc = 0; cc < NCHUNK; cc++) {
                double cs = (double)g_csum[b * NCHUNK + cc];
                if (run + cs > t) { c = cc; break; }
                run += cs;
            }
            if (c < 0) {  // fp edge: clamp to last chunk
                c = NCHUNK - 1;
                run = total - (double)g_csum[b * NCHUNK + NCHUNK - 1];
            }
            base = run;
        }
    }
    done = __shfl_sync(0xffffffffu, done, 0);
    if (done) {
        // never-taken path: full-row argmax of target (first max)
        float mv = -1.0f; int mi = 0;
        for (int i = lane; i < NV4; i += 32) {
            float4 t4 = tg[i];
            int e = i * 4;
            if (t4.x > mv) { mv = t4.x; mi = e; }
            if (t4.y > mv) { mv = t4.y; mi = e + 1; }
            if (t4.z > mv) { mv = t4.z; mi = e + 2; }
            if (t4.w > mv) { mv = t4.w; mi = e + 3; }
        }
#pragma unroll
        for (int off = 16; off; off >>= 1) {
            float ov = __shfl_down_sync(0xffffffffu, mv, off);
            int   oi = __shfl_down_sync(0xffffffffu, mi, off);
            if (ov > mv || (ov == mv && oi < mi)) { mv = ov; mi = oi; }
        }
        if (lane == 0) out[b * (K + 1) + g_num[b]] = (float)mi;
        return;
    }
    c    = __shfl_sync(0xffffffffu, c, 0);
    t    = __shfl_sync(0xffffffffu, t, 0);
    base = __shfl_sync(0xffffffffu, base, 0);

    // per-lane contiguous sub-chunk sums (25 float4 each), fp32
    int lb = c * CHUNK4 + lane * LANE4;
    float lsum = 0.0f;
#pragma unroll
    for (int k2 = 0; k2 < LANE4; k2++) {
        float4 t4 = tg[lb + k2];
        float4 d4 = dr[lb + k2];
        lsum += fmaxf(t4.x - d4.x, 0.0f) + fmaxf(t4.y - d4.y, 0.0f)
              + fmaxf(t4.z - d4.z, 0.0f) + fmaxf(t4.w - d4.w, 0.0f);
    }
    // inclusive warp scan over lane sums (fp64, 32 adds — trivial)
    double sc = (double)lsum;
#pragma unroll
    for (int off = 1; off < 32; off <<= 1) {
        double o = __shfl_up_sync(0xffffffffu, sc, off);
        if (lane >= off) sc += o;
    }
    unsigned m = __ballot_sync(0xffffffffu, (base + sc) > t);
    int fl = m ? (__ffs(m) - 1) : 31;  // clamp to last lane on fp edge

    if (lane == fl) {
        double run = base + (sc - (double)lsum);   // exclusive prefix for this lane
        int idx = (lb + LANE4 - 1) * 4 + 3;        // clamp default: last element
        for (int k2 = 0; k2 < LANE4; k2++) {
            float4 t4 = tg[lb + k2];
            float4 d4 = dr[lb + k2];
            double r0 = (double)fmaxf(t4.x - d4.x, 0.0f);
            double p1 = r0 + (double)fmaxf(t4.y - d4.y, 0.0f);
            double p2 = p1 + (double)fmaxf(t4.z - d4.z, 0.0f);
            double p3 = p2 + (double)fmaxf(t4.w - d4.w, 0.0f);
            int e = (lb + k2) * 4;
            if      (run + r0 > t) { idx = e;     break; }
            else if (run + p1 > t) { idx = e + 1; break; }
            else if (run + p2 > t) { idx = e + 2; break; }
            else if (run + p3 > t) { idx = e + 3; break; }
            run += p3;
        }
        out[b * (K + 1) + g_num[b]] = (float)idx;
    }
}

// ---------------------------------------------------------------------------
extern "C" void kernel_launch(void* const* d_in, const int* in_sizes, int n_in,
                              void* d_out, int out_size) {
    const int*   draft_ids    = (const int*)d_in[0];
    const float* draft_probs  = (const float*)d_in[1];
    const float* target_probs = (const float*)d_in[2];
    const int*   bonus        = (const int*)d_in[3];
    const float* uniforms     = (const float*)d_in[4];
    float* out = (float*)d_out;

    k1_accept<<<1, B * K>>>(draft_ids, draft_probs, target_probs, bonus,
                            uniforms, out, out_size);
    k2a_sums<<<B * SPLIT, NWARP * 32>>>(draft_probs, target_probs);
    k2b_pick<<<B, 32>>>(draft_probs, target_probs, out);
}